// round 1
// baseline (speedup 1.0000x reference)
#include <cuda_runtime.h>
#include <cuda_bf16.h>
#include <math.h>

// StyleLoss: x, target [B=8, C=256, H=128, W=128] fp32.
// loss = sum_{k=1..5} sqrt( sum_c (mu_k_x[c] - mu_k_t[c])^2 )
// where mu_1 = mean over (B,H,W) and mu_k (k>=2) are central moments.
//
// Single-pass strategy: accumulate raw power sums S1..S5 per channel for both
// tensors (one read of each tensor only), then convert to central moments via
// binomial identities in a tiny finalize kernel.

#define B_DIM 8
#define C_DIM 256
#define HW_DIM (128 * 128)          // 16384 contiguous floats per (b,c) slice
#define N_PER_CH (B_DIM * HW_DIM)   // 131072 elements reduced per channel
#define N_CTA (B_DIM * C_DIM)       // 2048 blocks, one per (b,c) slice

// Per-CTA partial sums: [cta][10] = {S1..S5 of x, S1..S5 of target}.
// Every slot is written every launch -> no zeroing needed, fully deterministic.
__device__ float g_part[N_CTA * 10];

__device__ __forceinline__ void acc5(float v, float* s) {
    float v2 = v * v;
    s[0] += v;
    s[1] = fmaf(v, v, s[1]);      // v^2
    s[2] = fmaf(v2, v, s[2]);     // v^3
    s[3] = fmaf(v2, v2, s[3]);    // v^4
    float v3 = v2 * v;
    s[4] = fmaf(v3, v2, s[4]);    // v^5
}

__global__ __launch_bounds__(256) void style_accum(const float* __restrict__ x,
                                                   const float* __restrict__ t) {
    const int cta = blockIdx.x;  // cta = b*C + c  -> contiguous HW slice
    const float4* __restrict__ xp =
        reinterpret_cast<const float4*>(x) + (size_t)cta * (HW_DIM / 4);
    const float4* __restrict__ tp =
        reinterpret_cast<const float4*>(t) + (size_t)cta * (HW_DIM / 4);

    float s[10];
#pragma unroll
    for (int j = 0; j < 10; j++) s[j] = 0.0f;

    // 16 float4 iterations per thread per tensor; fully coalesced.
#pragma unroll 4
    for (int i = threadIdx.x; i < HW_DIM / 4; i += 256) {
        float4 v = xp[i];
        float4 w = tp[i];
        acc5(v.x, s); acc5(v.y, s); acc5(v.z, s); acc5(v.w, s);
        acc5(w.x, s + 5); acc5(w.y, s + 5); acc5(w.z, s + 5); acc5(w.w, s + 5);
    }

    // Warp-level tree reduce of each of the 10 accumulators.
#pragma unroll
    for (int j = 0; j < 10; j++) {
#pragma unroll
        for (int o = 16; o > 0; o >>= 1)
            s[j] += __shfl_down_sync(0xffffffffu, s[j], o);
    }

    __shared__ float red[8][10];
    const int lane = threadIdx.x & 31;
    const int wid  = threadIdx.x >> 5;
    if (lane == 0) {
#pragma unroll
        for (int j = 0; j < 10; j++) red[wid][j] = s[j];
    }
    __syncthreads();

    if (threadIdx.x < 10) {
        float v = 0.0f;
#pragma unroll
        for (int w = 0; w < 8; w++) v += red[w][threadIdx.x];
        g_part[cta * 10 + threadIdx.x] = v;
    }
}

__global__ __launch_bounds__(256) void style_finalize(float* __restrict__ out) {
    const int c = threadIdx.x;  // one thread per channel

    float s[10];
#pragma unroll
    for (int j = 0; j < 10; j++) s[j] = 0.0f;
#pragma unroll
    for (int b = 0; b < B_DIM; b++) {
        const float* p = g_part + (size_t)(b * C_DIM + c) * 10;
#pragma unroll
        for (int j = 0; j < 10; j++) s[j] += p[j];
    }

    const float invN = 1.0f / (float)N_PER_CH;
    float d[5];
    {
        float m  = s[0] * invN, M2 = s[1] * invN, M3 = s[2] * invN,
              M4 = s[3] * invN, M5 = s[4] * invN;
        float n  = s[5] * invN, T2 = s[6] * invN, T3 = s[7] * invN,
              T4 = s[8] * invN, T5 = s[9] * invN;

        float m2 = m * m, m3 = m2 * m;
        float mu2x = M2 - m2;
        float mu3x = M3 - 3.0f * m * M2 + 2.0f * m3;
        float mu4x = M4 - 4.0f * m * M3 + 6.0f * m2 * M2 - 3.0f * m2 * m2;
        float mu5x = M5 - 5.0f * m * M4 + 10.0f * m2 * M3 - 10.0f * m3 * M2
                     + 4.0f * m3 * m2;

        float n2 = n * n, n3 = n2 * n;
        float mu2t = T2 - n2;
        float mu3t = T3 - 3.0f * n * T2 + 2.0f * n3;
        float mu4t = T4 - 4.0f * n * T3 + 6.0f * n2 * T2 - 3.0f * n2 * n2;
        float mu5t = T5 - 5.0f * n * T4 + 10.0f * n2 * T3 - 10.0f * n3 * T2
                     + 4.0f * n3 * n2;

        d[0] = m - n;
        d[1] = mu2x - mu2t;
        d[2] = mu3x - mu3t;
        d[3] = mu4x - mu4t;
        d[4] = mu5x - mu5t;
    }

    __shared__ float red[5][C_DIM];
#pragma unroll
    for (int i = 0; i < 5; i++) red[i][c] = d[i] * d[i];
    __syncthreads();

    for (int off = 128; off > 0; off >>= 1) {
        if (c < off) {
#pragma unroll
            for (int i = 0; i < 5; i++) red[i][c] += red[i][c + off];
        }
        __syncthreads();
    }

    if (c == 0) {
        out[0] = sqrtf(red[0][0]) + sqrtf(red[1][0]) + sqrtf(red[2][0]) +
                 sqrtf(red[3][0]) + sqrtf(red[4][0]);
    }
}

extern "C" void kernel_launch(void* const* d_in, const int* in_sizes, int n_in,
                              void* d_out, int out_size) {
    const float* x = (const float*)d_in[0];
    const float* t = (const float*)d_in[1];
    float* out = (float*)d_out;

    style_accum<<<N_CTA, 256>>>(x, t);
    style_finalize<<<1, C_DIM>>>(out);
}